// round 9
// baseline (speedup 1.0000x reference)
#include <cuda_runtime.h>
#include <math.h>

#define Hh 192
#define Ww 192
#define Cc 64
#define Bb 2
#define SH 384
#define SW 384

// Scratch (device globals; no allocation allowed)
__device__ float g_feat[Bb * Hh * Ww * Cc];   // [b][y][x][c]  channel-last, 18.9MB
__device__ float g_WCt[64 * 32];              // [c][e*8+k]
__device__ float g_WEt[32 * 64];              // [e*8+k][c]
__device__ float g_routing4[4][4];            // [parity][expert]
__device__ float g_offset4[4][2];             // [parity][x,y]

// ---------------------------------------------------------------------------
// Kernel B: parity-table MLP (4 combos) + weight transposes. 1 block.
// ---------------------------------------------------------------------------
__global__ void precompute_kernel(
    const float* __restrict__ wc_e, const float* __restrict__ we_e,
    const float* __restrict__ w1, const float* __restrict__ b1,
    const float* __restrict__ w2, const float* __restrict__ b2,
    const float* __restrict__ wr, const float* __restrict__ br,
    const float* __restrict__ wo, const float* __restrict__ bo)
{
    int t = threadIdx.x;
    // Transposed expert tables
    for (int idx = t; idx < 2048; idx += 256) {
        int ek = idx >> 6;          // e*8+k
        int c  = idx & 63;
        int e  = ek >> 3, k = ek & 7;
        g_WCt[c * 32 + ek] = wc_e[(e * 8 + k) * 64 + c];   // weight_compress[e][k][c]
        g_WEt[ek * 64 + c] = we_e[e * 512 + c * 8 + k];    // weight_expand[e][c][k]
    }
    if (t < 4) {
        int pi = t >> 1, pj = t & 1;
        // exact reference formulas (scale = scale2 = 2)
        float ih = (pi + 0.5f) * 0.5f;
        float ch = ih - floorf(ih + 0.001f) - 0.5f;
        float iw = (pj + 0.5f) * 0.5f;
        float cw = iw - floorf(iw + 0.001f) - 0.5f;
        float inp[4] = {0.5f, 0.5f, ch, cw};   // {1/scale2, 1/scale, coor_h, coor_w}
        float h1[64], h2[64];
        for (int o = 0; o < 64; o++) {
            float a = b1[o];
            for (int i = 0; i < 4; i++) a += w1[o * 4 + i] * inp[i];
            h1[o] = fmaxf(a, 0.f);
        }
        for (int o = 0; o < 64; o++) {
            float a = b2[o];
            for (int i = 0; i < 64; i++) a += w2[o * 64 + i] * h1[i];
            h2[o] = fmaxf(a, 0.f);
        }
        for (int d = 0; d < 2; d++) {
            float a = bo[d];
            for (int i = 0; i < 64; i++) a += wo[d * 64 + i] * h2[i];
            g_offset4[t][d] = a;
        }
        for (int e = 0; e < 4; e++) {
            float a = br[e];
            for (int i = 0; i < 64; i++) a += wr[e * 64 + i] * h2[i];
            g_routing4[t][e] = 1.f / (1.f + expf(-a));
        }
    }
}

// ---------------------------------------------------------------------------
// Kernel A: feat = conv1x1(w_conv, [x, sobel_x, sobel_y]) with Sobel fused.
// One thread per input pixel, one block per row. Output channel-last.
// ---------------------------------------------------------------------------
__global__ __launch_bounds__(192) void conv_feat_kernel(
    const float* __restrict__ x, const float* __restrict__ wconv,
    const float* __restrict__ bconv)
{
    __shared__ float2 wp01[64][64];   // (w_val, w_gx) [c][o]
    __shared__ float  wp2[64][64];    // w_gy        [c][o]
    int t = threadIdx.x;
    for (int idx = t; idx < 4096; idx += 192) {
        int c = idx >> 6, o = idx & 63;
        wp01[c][o] = make_float2(wconv[o * 192 + c], wconv[o * 192 + 64 + c]);
        wp2[c][o]  = wconv[o * 192 + 128 + c];
    }
    __syncthreads();

    int y = blockIdx.x, b = blockIdx.y, xc = t;
    float acc[64];
    #pragma unroll
    for (int o = 0; o < 64; o++) acc[o] = __ldg(&bconv[o]);

    const bool t_ok = y > 0, bt_ok = y < Hh - 1, l_ok = xc > 0, r_ok = xc < Ww - 1;
    const float* xp = x + (((size_t)b * 64) * Hh + y) * Ww + xc;

    for (int c = 0; c < 64; c++) {
        const float* p = xp + (size_t)c * Hh * Ww;
        float mm = p[0];
        float ml = l_ok ? p[-1] : 0.f;
        float mr = r_ok ? p[1] : 0.f;
        float tm = 0.f, tl = 0.f, tr = 0.f, bm = 0.f, bl = 0.f, br2 = 0.f;
        if (t_ok)  { tm = p[-Ww]; tl = l_ok ? p[-Ww - 1] : 0.f; tr  = r_ok ? p[-Ww + 1] : 0.f; }
        if (bt_ok) { bm = p[ Ww]; bl = l_ok ? p[ Ww - 1] : 0.f; br2 = r_ok ? p[ Ww + 1] : 0.f; }
        float gx = (tr - tl) + 2.f * (mr - ml) + (br2 - bl);
        float gy = (bl - tl) + 2.f * (bm - tm) + (br2 - tr);
        #pragma unroll
        for (int o = 0; o < 64; o++) {
            float2 w01 = wp01[c][o];
            acc[o] += w01.x * mm + w01.y * gx + wp2[c][o] * gy;
        }
    }
    float* fp = g_feat + ((((size_t)b * Hh + y) * Ww) + xc) * 64;
    #pragma unroll
    for (int o = 0; o < 64; o += 4)
        *(float4*)(fp + o) = make_float4(acc[o], acc[o + 1], acc[o + 2], acc[o + 3]);
}

// ---------------------------------------------------------------------------
// Kernel C: per 32-pixel tile: bilinear gather + expert mixture + residual.
// ---------------------------------------------------------------------------
__global__ __launch_bounds__(256) void main_kernel(float* __restrict__ out)
{
    __shared__ float s_fea0[32][65];
    __shared__ float s_WC[64][32];
    __shared__ float s_WE[32][64];
    __shared__ float s_midall[32][33];
    __shared__ float s_midx[32][33];
    __shared__ float s_w[4][32];
    __shared__ int   s_tap[4][32];
    __shared__ float s_r[4][32];

    int t = threadIdx.x;
    int j0 = blockIdx.x * 32, i = blockIdx.y, b = blockIdx.z;

    for (int idx = t; idx < 2048; idx += 256) {
        s_WC[idx >> 5][idx & 31] = g_WCt[idx];
        s_WE[idx >> 6][idx & 63] = g_WEt[idx];
    }

    if (t < 32) {
        int p = t, j = j0 + p;
        int pc = ((i & 1) << 1) | (j & 1);
        float offx = g_offset4[pc][0];
        float offy = g_offset4[pc][1];
        #pragma unroll
        for (int e = 0; e < 4; e++) s_r[e][p] = g_routing4[pc][e];

        const float inv_wm1 = 2.f / (Ww - 1), inv_hm1 = 2.f / (Hh - 1);
        float gx0 = ((j + 0.5f) * 0.5f - 0.5f) * inv_wm1 - 1.f;
        float gy0 = ((i + 0.5f) * 0.5f - 0.5f) * inv_hm1 - 1.f;
        float gxv = gx0 + offx * inv_wm1;
        float gyv = gy0 + offy * inv_hm1;
        float ix = ((gxv + 1.f) * (float)Ww - 1.f) * 0.5f;
        float iy = ((gyv + 1.f) * (float)Hh - 1.f) * 0.5f;
        float x0f = floorf(ix), y0f = floorf(iy);
        float wx1 = ix - x0f, wx0 = 1.f - wx1;
        float wy1 = iy - y0f, wy0 = 1.f - wy1;
        float x1f = x0f + 1.f, y1f = y0f + 1.f;
        float vx0 = (x0f >= 0.f && x0f <= (float)(Ww - 1)) ? 1.f : 0.f;
        float vx1 = (x1f >= 0.f && x1f <= (float)(Ww - 1)) ? 1.f : 0.f;
        float vy0 = (y0f >= 0.f && y0f <= (float)(Hh - 1)) ? 1.f : 0.f;
        float vy1 = (y1f >= 0.f && y1f <= (float)(Hh - 1)) ? 1.f : 0.f;
        int xi0 = min(max((int)x0f, 0), Ww - 1);
        int xi1 = min(max((int)x1f, 0), Ww - 1);
        int yi0 = min(max((int)y0f, 0), Hh - 1);
        int yi1 = min(max((int)y1f, 0), Hh - 1);
        s_w[0][p] = wx0 * wy0 * vx0 * vy0;
        s_w[1][p] = wx1 * wy0 * vx1 * vy0;
        s_w[2][p] = wx0 * wy1 * vx0 * vy1;
        s_w[3][p] = wx1 * wy1 * vx1 * vy1;
        s_tap[0][p] = (yi0 * Ww + xi0) * 64;
        s_tap[1][p] = (yi0 * Ww + xi1) * 64;
        s_tap[2][p] = (yi1 * Ww + xi0) * 64;
        s_tap[3][p] = (yi1 * Ww + xi1) * 64;
    }
    __syncthreads();

    // Phase 2: bilinear gather -> s_fea0
    {
        int p = t >> 3, c0 = (t & 7) * 8;
        const float* base = g_feat + (size_t)b * Hh * Ww * 64 + c0;
        float4 a0 = make_float4(0, 0, 0, 0), a1 = make_float4(0, 0, 0, 0);
        #pragma unroll
        for (int tp = 0; tp < 4; tp++) {
            float wgt = s_w[tp][p];
            const float* q = base + s_tap[tp][p];
            float4 v0 = *(const float4*)q;
            float4 v1 = *(const float4*)(q + 4);
            a0.x += wgt * v0.x; a0.y += wgt * v0.y; a0.z += wgt * v0.z; a0.w += wgt * v0.w;
            a1.x += wgt * v1.x; a1.y += wgt * v1.y; a1.z += wgt * v1.z; a1.w += wgt * v1.w;
        }
        s_fea0[p][c0 + 0] = a0.x; s_fea0[p][c0 + 1] = a0.y;
        s_fea0[p][c0 + 2] = a0.z; s_fea0[p][c0 + 3] = a0.w;
        s_fea0[p][c0 + 4] = a1.x; s_fea0[p][c0 + 5] = a1.y;
        s_fea0[p][c0 + 6] = a1.z; s_fea0[p][c0 + 7] = a1.w;
    }
    __syncthreads();

    // Phase 3: mid_all[p][e*8+k] = sum_c fea0[p][c] * wc_e[k][c]
    {
        int p = t >> 3, ek0 = (t & 7) * 4;
        float a0 = 0.f, a1 = 0.f, a2 = 0.f, a3 = 0.f;
        #pragma unroll
        for (int c = 0; c < 64; c++) {
            float f = s_fea0[p][c];
            a0 += f * s_WC[c][ek0 + 0];
            a1 += f * s_WC[c][ek0 + 1];
            a2 += f * s_WC[c][ek0 + 2];
            a3 += f * s_WC[c][ek0 + 3];
        }
        s_midall[p][ek0 + 0] = a0; s_midall[p][ek0 + 1] = a1;
        s_midall[p][ek0 + 2] = a2; s_midall[p][ek0 + 3] = a3;
    }
    __syncthreads();

    // Phase 3b: routing combine + routing-scaled expansion inputs
    {
        int p = t >> 3, k = t & 7;
        float m = 0.f;
        #pragma unroll
        for (int e = 0; e < 4; e++) m += s_r[e][p] * s_midall[p][e * 8 + k];
        #pragma unroll
        for (int e = 0; e < 4; e++) s_midx[p][e * 8 + k] = s_r[e][p] * m;
    }
    __syncthreads();

    // Phase 4a: out_delta[p][c] = sum_ek midx[p][ek] * we_e[c][k]; accumulate into fea0
    {
        int p = t >> 3, c0 = (t & 7) * 8;
        float a[8] = {0.f, 0.f, 0.f, 0.f, 0.f, 0.f, 0.f, 0.f};
        #pragma unroll
        for (int ek = 0; ek < 32; ek++) {
            float m = s_midx[p][ek];
            #pragma unroll
            for (int n = 0; n < 8; n++) a[n] += m * s_WE[ek][c0 + n];
        }
        #pragma unroll
        for (int n = 0; n < 8; n++) s_fea0[p][c0 + n] += a[n];
    }
    __syncthreads();

    // Phase 4b: coalesced writes (lane = pixel along j)
    {
        int w = t >> 5, p = t & 31;
        float* op = out + (((size_t)b * 64) * SH + i) * SW + j0 + p;
        #pragma unroll
        for (int n = 0; n < 8; n++) {
            int c = w * 8 + n;
            op[(size_t)c * SH * SW] = s_fea0[p][c];
        }
    }
}

// ---------------------------------------------------------------------------
extern "C" void kernel_launch(void* const* d_in, const int* in_sizes, int n_in,
                              void* d_out, int out_size)
{
    const float* x    = (const float*)d_in[0];
    const float* wc_e = (const float*)d_in[1];
    const float* we_e = (const float*)d_in[2];
    const float* w1   = (const float*)d_in[3];
    const float* b1   = (const float*)d_in[4];
    const float* w2   = (const float*)d_in[5];
    const float* b2   = (const float*)d_in[6];
    const float* wr   = (const float*)d_in[7];
    const float* br   = (const float*)d_in[8];
    const float* wo   = (const float*)d_in[9];
    const float* bo   = (const float*)d_in[10];
    const float* wcv  = (const float*)d_in[11];
    const float* bcv  = (const float*)d_in[12];

    precompute_kernel<<<1, 256>>>(wc_e, we_e, w1, b1, w2, b2, wr, br, wo, bo);
    conv_feat_kernel<<<dim3(Hh, Bb), 192>>>(x, wcv, bcv);
    main_kernel<<<dim3(SW / 32, SH, Bb), 256>>>((float*)d_out);
}

// round 13
// speedup vs baseline: 1.3900x; 1.3900x over previous
#include <cuda_runtime.h>
#include <math.h>

#define Hh 192
#define Ww 192
#define Cc 64
#define Bb 2
#define SH 384
#define SW 384

// Scratch (device globals; no allocation allowed)
__device__ float g_feat[Bb * Hh * Ww * Cc];   // [b][y][x][c]  channel-last, 18.9MB
__device__ float g_WCt[64 * 32];              // [c][e*8+k]
__device__ float g_WEt[32 * 64];              // [e*8+k][c]
__device__ float g_routing4[4][4];            // [parity][expert]
__device__ float g_offset4[4][2];             // [parity][x,y]

// ---------------------------------------------------------------------------
// Kernel B: parity-table MLP (4 combos) + weight transposes. 1 block, but now
// fully parallel: combo = t>>6, neuron o = t&63. Same summation order as the
// serial version -> bit-identical results.
// ---------------------------------------------------------------------------
__global__ __launch_bounds__(256) void precompute_kernel(
    const float* __restrict__ wc_e, const float* __restrict__ we_e,
    const float* __restrict__ w1, const float* __restrict__ b1,
    const float* __restrict__ w2, const float* __restrict__ b2,
    const float* __restrict__ wr, const float* __restrict__ br,
    const float* __restrict__ wo, const float* __restrict__ bo)
{
    __shared__ float s_h1[4][64];
    __shared__ float s_h2[4][64];
    int t = threadIdx.x;

    // Transposed expert tables (independent of MLP work)
    for (int idx = t; idx < 2048; idx += 256) {
        int ek = idx >> 6;          // e*8+k
        int c  = idx & 63;
        int e  = ek >> 3, k = ek & 7;
        g_WCt[c * 32 + ek] = wc_e[(e * 8 + k) * 64 + c];   // weight_compress[e][k][c]
        g_WEt[ek * 64 + c] = we_e[e * 512 + c * 8 + k];    // weight_expand[e][c][k]
    }

    int combo = t >> 6;   // parity combo 0..3
    int o     = t & 63;   // neuron index
    int pi = combo >> 1, pj = combo & 1;

    // exact reference formulas (scale = scale2 = 2)
    float ih = (pi + 0.5f) * 0.5f;
    float ch = ih - floorf(ih + 0.001f) - 0.5f;
    float iw = (pj + 0.5f) * 0.5f;
    float cw = iw - floorf(iw + 0.001f) - 0.5f;
    float inp[4] = {0.5f, 0.5f, ch, cw};

    // layer 1: h1[o]
    {
        float a = b1[o];
        #pragma unroll
        for (int i = 0; i < 4; i++) a += w1[o * 4 + i] * inp[i];
        s_h1[combo][o] = fmaxf(a, 0.f);
    }
    __syncthreads();

    // layer 2: h2[o]
    {
        float a = b2[o];
        #pragma unroll 8
        for (int i = 0; i < 64; i++) a += w2[o * 64 + i] * s_h1[combo][i];
        s_h2[combo][o] = fmaxf(a, 0.f);
    }
    __syncthreads();

    // heads: 2 offsets + 4 routing per combo
    if (o < 2) {
        float a = bo[o];
        #pragma unroll 8
        for (int i = 0; i < 64; i++) a += wo[o * 64 + i] * s_h2[combo][i];
        g_offset4[combo][o] = a;
    } else if (o < 6) {
        int e = o - 2;
        float a = br[e];
        #pragma unroll 8
        for (int i = 0; i < 64; i++) a += wr[e * 64 + i] * s_h2[combo][i];
        g_routing4[combo][e] = 1.f / (1.f + expf(-a));
    }
}

// ---------------------------------------------------------------------------
// Kernel A: feat = conv1x1(w_conv, [x, sobel_x, sobel_y]) with Sobel fused.
// Weights staged as float4 over the output dim -> 48 broadcast LDS.128 per
// channel instead of 128 narrow LDS.
// ---------------------------------------------------------------------------
__global__ __launch_bounds__(192) void conv_feat_kernel(
    const float* __restrict__ x, const float* __restrict__ wconv,
    const float* __restrict__ bconv)
{
    __shared__ float4 w0q[64][16];   // value weight,   [c][o/4]
    __shared__ float4 w1q[64][16];   // gx weight
    __shared__ float4 w2q[64][16];   // gy weight
    int t = threadIdx.x;
    for (int idx = t; idx < 1024; idx += 192) {
        int c = idx >> 4, og = idx & 15;
        int o = og * 4;
        w0q[c][og] = make_float4(wconv[(o + 0) * 192 + c], wconv[(o + 1) * 192 + c],
                                 wconv[(o + 2) * 192 + c], wconv[(o + 3) * 192 + c]);
        w1q[c][og] = make_float4(wconv[(o + 0) * 192 + 64 + c], wconv[(o + 1) * 192 + 64 + c],
                                 wconv[(o + 2) * 192 + 64 + c], wconv[(o + 3) * 192 + 64 + c]);
        w2q[c][og] = make_float4(wconv[(o + 0) * 192 + 128 + c], wconv[(o + 1) * 192 + 128 + c],
                                 wconv[(o + 2) * 192 + 128 + c], wconv[(o + 3) * 192 + 128 + c]);
    }
    __syncthreads();

    int y = blockIdx.x, b = blockIdx.y, xc = t;
    float acc[64];
    #pragma unroll
    for (int o = 0; o < 64; o++) acc[o] = __ldg(&bconv[o]);

    const bool t_ok = y > 0, bt_ok = y < Hh - 1, l_ok = xc > 0, r_ok = xc < Ww - 1;
    const float* xp = x + (((size_t)b * 64) * Hh + y) * Ww + xc;

    for (int c = 0; c < 64; c++) {
        const float* p = xp + (size_t)c * Hh * Ww;
        float mm = p[0];
        float ml = l_ok ? p[-1] : 0.f;
        float mr = r_ok ? p[1] : 0.f;
        float tm = 0.f, tl = 0.f, tr = 0.f, bm = 0.f, bl = 0.f, br2 = 0.f;
        if (t_ok)  { tm = p[-Ww]; tl = l_ok ? p[-Ww - 1] : 0.f; tr  = r_ok ? p[-Ww + 1] : 0.f; }
        if (bt_ok) { bm = p[ Ww]; bl = l_ok ? p[ Ww - 1] : 0.f; br2 = r_ok ? p[ Ww + 1] : 0.f; }
        float gx = (tr - tl) + 2.f * (mr - ml) + (br2 - bl);
        float gy = (bl - tl) + 2.f * (bm - tm) + (br2 - tr);
        #pragma unroll
        for (int og = 0; og < 16; og++) {
            float4 a = w0q[c][og];
            float4 g = w1q[c][og];
            float4 h = w2q[c][og];
            acc[og * 4 + 0] += a.x * mm + g.x * gx + h.x * gy;
            acc[og * 4 + 1] += a.y * mm + g.y * gx + h.y * gy;
            acc[og * 4 + 2] += a.z * mm + g.z * gx + h.z * gy;
            acc[og * 4 + 3] += a.w * mm + g.w * gx + h.w * gy;
        }
    }
    float* fp = g_feat + ((((size_t)b * Hh + y) * Ww) + xc) * 64;
    #pragma unroll
    for (int o = 0; o < 64; o += 4)
        *(float4*)(fp + o) = make_float4(acc[o], acc[o + 1], acc[o + 2], acc[o + 3]);
}

// ---------------------------------------------------------------------------
// Kernel C: per 32-pixel tile: bilinear gather + expert mixture + residual.
// s_fea0 stride 68 keeps float4 alignment; GEMM-let phases vectorized.
// ---------------------------------------------------------------------------
__global__ __launch_bounds__(256) void main_kernel(float* __restrict__ out)
{
    __shared__ float s_fea0[32][68];
    __shared__ float s_WC[64][32];
    __shared__ float s_WE[32][64];
    __shared__ float s_midall[32][33];
    __shared__ float s_midx[32][33];
    __shared__ float s_w[4][32];
    __shared__ int   s_tap[4][32];
    __shared__ float s_r[4][32];

    int t = threadIdx.x;
    int j0 = blockIdx.x * 32, i = blockIdx.y, b = blockIdx.z;

    for (int idx = t; idx < 2048; idx += 256) {
        s_WC[idx >> 5][idx & 31] = g_WCt[idx];
        s_WE[idx >> 6][idx & 63] = g_WEt[idx];
    }

    if (t < 32) {
        int p = t, j = j0 + p;
        int pc = ((i & 1) << 1) | (j & 1);
        float offx = g_offset4[pc][0];
        float offy = g_offset4[pc][1];
        #pragma unroll
        for (int e = 0; e < 4; e++) s_r[e][p] = g_routing4[pc][e];

        const float inv_wm1 = 2.f / (Ww - 1), inv_hm1 = 2.f / (Hh - 1);
        float gx0 = ((j + 0.5f) * 0.5f - 0.5f) * inv_wm1 - 1.f;
        float gy0 = ((i + 0.5f) * 0.5f - 0.5f) * inv_hm1 - 1.f;
        float gxv = gx0 + offx * inv_wm1;
        float gyv = gy0 + offy * inv_hm1;
        float ix = ((gxv + 1.f) * (float)Ww - 1.f) * 0.5f;
        float iy = ((gyv + 1.f) * (float)Hh - 1.f) * 0.5f;
        float x0f = floorf(ix), y0f = floorf(iy);
        float wx1 = ix - x0f, wx0 = 1.f - wx1;
        float wy1 = iy - y0f, wy0 = 1.f - wy1;
        float x1f = x0f + 1.f, y1f = y0f + 1.f;
        float vx0 = (x0f >= 0.f && x0f <= (float)(Ww - 1)) ? 1.f : 0.f;
        float vx1 = (x1f >= 0.f && x1f <= (float)(Ww - 1)) ? 1.f : 0.f;
        float vy0 = (y0f >= 0.f && y0f <= (float)(Hh - 1)) ? 1.f : 0.f;
        float vy1 = (y1f >= 0.f && y1f <= (float)(Hh - 1)) ? 1.f : 0.f;
        int xi0 = min(max((int)x0f, 0), Ww - 1);
        int xi1 = min(max((int)x1f, 0), Ww - 1);
        int yi0 = min(max((int)y0f, 0), Hh - 1);
        int yi1 = min(max((int)y1f, 0), Hh - 1);
        s_w[0][p] = wx0 * wy0 * vx0 * vy0;
        s_w[1][p] = wx1 * wy0 * vx1 * vy0;
        s_w[2][p] = wx0 * wy1 * vx0 * vy1;
        s_w[3][p] = wx1 * wy1 * vx1 * vy1;
        s_tap[0][p] = (yi0 * Ww + xi0) * 64;
        s_tap[1][p] = (yi0 * Ww + xi1) * 64;
        s_tap[2][p] = (yi1 * Ww + xi0) * 64;
        s_tap[3][p] = (yi1 * Ww + xi1) * 64;
    }
    __syncthreads();

    // Phase 2: bilinear gather -> s_fea0
    {
        int p = t >> 3, c0 = (t & 7) * 8;
        const float* base = g_feat + (size_t)b * Hh * Ww * 64 + c0;
        float4 a0 = make_float4(0, 0, 0, 0), a1 = make_float4(0, 0, 0, 0);
        #pragma unroll
        for (int tp = 0; tp < 4; tp++) {
            float wgt = s_w[tp][p];
            const float* q = base + s_tap[tp][p];
            float4 v0 = *(const float4*)q;
            float4 v1 = *(const float4*)(q + 4);
            a0.x += wgt * v0.x; a0.y += wgt * v0.y; a0.z += wgt * v0.z; a0.w += wgt * v0.w;
            a1.x += wgt * v1.x; a1.y += wgt * v1.y; a1.z += wgt * v1.z; a1.w += wgt * v1.w;
        }
        *(float4*)&s_fea0[p][c0]     = a0;
        *(float4*)&s_fea0[p][c0 + 4] = a1;
    }
    __syncthreads();

    // Phase 3: mid_all[p][e*8+k] = sum_c fea0[p][c] * wc_e[k][c]  (vectorized)
    {
        int p = t >> 3, ek0 = (t & 7) * 4;
        float a0 = 0.f, a1 = 0.f, a2 = 0.f, a3 = 0.f;
        #pragma unroll
        for (int c4 = 0; c4 < 16; c4++) {
            float4 f = *(const float4*)&s_fea0[p][c4 * 4];
            float4 wA = *(const float4*)&s_WC[c4 * 4 + 0][ek0];
            float4 wB = *(const float4*)&s_WC[c4 * 4 + 1][ek0];
            float4 wC = *(const float4*)&s_WC[c4 * 4 + 2][ek0];
            float4 wD = *(const float4*)&s_WC[c4 * 4 + 3][ek0];
            a0 += f.x * wA.x + f.y * wB.x + f.z * wC.x + f.w * wD.x;
            a1 += f.x * wA.y + f.y * wB.y + f.z * wC.y + f.w * wD.y;
            a2 += f.x * wA.z + f.y * wB.z + f.z * wC.z + f.w * wD.z;
            a3 += f.x * wA.w + f.y * wB.w + f.z * wC.w + f.w * wD.w;
        }
        s_midall[p][ek0 + 0] = a0; s_midall[p][ek0 + 1] = a1;
        s_midall[p][ek0 + 2] = a2; s_midall[p][ek0 + 3] = a3;
    }
    __syncthreads();

    // Phase 3b: routing combine + routing-scaled expansion inputs
    {
        int p = t >> 3, k = t & 7;
        float m = 0.f;
        #pragma unroll
        for (int e = 0; e < 4; e++) m += s_r[e][p] * s_midall[p][e * 8 + k];
        #pragma unroll
        for (int e = 0; e < 4; e++) s_midx[p][e * 8 + k] = s_r[e][p] * m;
    }
    __syncthreads();

    // Phase 4a: out_delta[p][c] = sum_ek midx[p][ek] * we_e[c][k]; accumulate into fea0
    {
        int p = t >> 3, c0 = (t & 7) * 8;
        float4 A = make_float4(0, 0, 0, 0), B = make_float4(0, 0, 0, 0);
        #pragma unroll
        for (int ek = 0; ek < 32; ek++) {
            float m = s_midx[p][ek];
            float4 w0 = *(const float4*)&s_WE[ek][c0];
            float4 w1v = *(const float4*)&s_WE[ek][c0 + 4];
            A.x += m * w0.x;  A.y += m * w0.y;  A.z += m * w0.z;  A.w += m * w0.w;
            B.x += m * w1v.x; B.y += m * w1v.y; B.z += m * w1v.z; B.w += m * w1v.w;
        }
        float4 f0 = *(const float4*)&s_fea0[p][c0];
        float4 f1 = *(const float4*)&s_fea0[p][c0 + 4];
        f0.x += A.x; f0.y += A.y; f0.z += A.z; f0.w += A.w;
        f1.x += B.x; f1.y += B.y; f1.z += B.z; f1.w += B.w;
        *(float4*)&s_fea0[p][c0]     = f0;
        *(float4*)&s_fea0[p][c0 + 4] = f1;
    }
    __syncthreads();

    // Phase 4b: coalesced writes (lane = pixel along j)
    {
        int w = t >> 5, p = t & 31;
        float* op = out + (((size_t)b * 64) * SH + i) * SW + j0 + p;
        #pragma unroll
        for (int n = 0; n < 8; n++) {
            int c = w * 8 + n;
            op[(size_t)c * SH * SW] = s_fea0[p][c];
        }
    }
}

// ---------------------------------------------------------------------------
extern "C" void kernel_launch(void* const* d_in, const int* in_sizes, int n_in,
                              void* d_out, int out_size)
{
    const float* x    = (const float*)d_in[0];
    const float* wc_e = (const float*)d_in[1];
    const float* we_e = (const float*)d_in[2];
    const float* w1   = (const float*)d_in[3];
    const float* b1   = (const float*)d_in[4];
    const float* w2   = (const float*)d_in[5];
    const float* b2   = (const float*)d_in[6];
    const float* wr   = (const float*)d_in[7];
    const float* br   = (const float*)d_in[8];
    const float* wo   = (const float*)d_in[9];
    const float* bo   = (const float*)d_in[10];
    const float* wcv  = (const float*)d_in[11];
    const float* bcv  = (const float*)d_in[12];

    precompute_kernel<<<1, 256>>>(wc_e, we_e, w1, b1, w2, b2, wr, br, wo, bo);
    conv_feat_kernel<<<dim3(Hh, Bb), 192>>>(x, wcv, bcv);
    main_kernel<<<dim3(SW / 32, SH, Bb), 256>>>((float*)d_out);
}